// round 14
// baseline (speedup 1.0000x reference)
#include <cuda_runtime.h>
#include <cuda_fp16.h>
#include <math.h>
#include <stdint.h>

#define N_TOK 16384
#define KNN   32
#define DIM   512
#define FEXP  8
#define E2D   1024
#define LN_EPS 1e-5f

// ---------------- device scratch (allocation-free rule) ----------------
__device__ float  g_fnw[N_TOK * FEXP];
__device__ __align__(16) __half g_Ah[(size_t)N_TOK * E2D];           // inp fp16 [N,1024]
__device__ __align__(16) __half g_Bw[(size_t)16 * E2D * DIM];        // [em][k][d] fp16
__device__ __align__(16) __half g_h [(size_t)16 * N_TOK * DIM];      // activated h per em (fp16)

__device__ __forceinline__ unsigned smem_u32(const void* p) {
    return (unsigned)__cvta_generic_to_shared(p);
}
#define CP_ASYNC16(dst, src) asm volatile("cp.async.cg.shared.global [%0], [%1], 16;" :: "r"(dst), "l"(src))
#define CP_COMMIT() asm volatile("cp.async.commit_group;" ::: "memory")
#define CP_WAIT0()  asm volatile("cp.async.wait_group 0;" ::: "memory")
#define CP_WAIT1()  asm volatile("cp.async.wait_group 1;" ::: "memory")

#define LDSM4(r, addr) \
    asm volatile("ldmatrix.sync.aligned.m8n8.x4.shared.b16 {%0,%1,%2,%3}, [%4];" \
        : "=r"((r)[0]), "=r"((r)[1]), "=r"((r)[2]), "=r"((r)[3]) : "r"(addr))
#define LDSM4T(r, addr) \
    asm volatile("ldmatrix.sync.aligned.m8n8.x4.trans.shared.b16 {%0,%1,%2,%3}, [%4];" \
        : "=r"((r)[0]), "=r"((r)[1]), "=r"((r)[2]), "=r"((r)[3]) : "r"(addr))
#define MMA16816(d, a, b0, b1) \
    asm volatile("mma.sync.aligned.m16n8k16.row.col.f32.f16.f16.f32 " \
        "{%0,%1,%2,%3}, {%4,%5,%6,%7}, {%8,%9}, {%0,%1,%2,%3};" \
        : "+f"((d)[0]), "+f"((d)[1]), "+f"((d)[2]), "+f"((d)[3]) \
        : "r"((a)[0]), "r"((a)[1]), "r"((a)[2]), "r"((a)[3]), "r"(b0), "r"(b1))

// ---------------------------------------------------------------------------
// Kernel 1: per-row prep -> fnw + fp16 inp rows.
// __ldcs on single-use streams; k-loop unroll 8 for doubled MLP.
// ---------------------------------------------------------------------------
__global__ void prep_kernel(const float* __restrict__ token,
                            const float* __restrict__ routed,
                            const float* __restrict__ sim,
                            const float* __restrict__ selW,
                            const float* __restrict__ selb)
{
    const int n = blockIdx.x;
    const int t = threadIdx.x;           // 0..127

    __shared__ float wsm[KNN];
    __shared__ float partsm[4 * FEXP];

    if (t < KNN) {
        float s = sim[n * KNN + t];
        float m = s;
        #pragma unroll
        for (int o = 16; o; o >>= 1) m = fmaxf(m, __shfl_xor_sync(0xffffffffu, m, o));
        float e = expf(s - m);
        float sum = e;
        #pragma unroll
        for (int o = 16; o; o >>= 1) sum += __shfl_xor_sync(0xffffffffu, sum, o);
        wsm[t] = e / sum;
    }
    __syncthreads();

    float tok[4], acc[4];
    #pragma unroll
    for (int i = 0; i < 4; i++) {
        tok[i] = __ldcs(token + (size_t)n * DIM + t + i * 128);
        acc[i] = 0.f;
    }
    const float* rbase = routed + (size_t)n * KNN * DIM + t;
    #pragma unroll 8
    for (int k = 0; k < KNN; k++) {
        float wk = wsm[k];
        #pragma unroll
        for (int i = 0; i < 4; i++)
            acc[i] = fmaf(wk, __ldcs(rbase + (size_t)k * DIM + i * 128), acc[i]);
    }

    float part[FEXP];
    #pragma unroll
    for (int f = 0; f < FEXP; f++) part[f] = 0.f;
    #pragma unroll
    for (int i = 0; i < 4; i++) {
        int d = t + i * 128;
        #pragma unroll
        for (int f = 0; f < FEXP; f++)
            part[f] = fmaf(tok[i], selW[d * FEXP + f], part[f]);
    }
    #pragma unroll
    for (int f = 0; f < FEXP; f++) {
        float v = part[f];
        #pragma unroll
        for (int o = 16; o; o >>= 1) v += __shfl_xor_sync(0xffffffffu, v, o);
        if ((t & 31) == 0) partsm[(t >> 5) * FEXP + f] = v;
    }
    __syncthreads();
    if (t == 0) {
        float lg[FEXP];
        float m = -1e30f;
        #pragma unroll
        for (int f = 0; f < FEXP; f++) {
            lg[f] = selb[f] + partsm[f] + partsm[FEXP + f]
                  + partsm[2 * FEXP + f] + partsm[3 * FEXP + f];
            m = fmaxf(m, lg[f]);
        }
        float s = 0.f;
        #pragma unroll
        for (int f = 0; f < FEXP; f++) { lg[f] = expf(lg[f] - m); s += lg[f]; }
        float inv = 1.f / s;
        #pragma unroll
        for (int f = 0; f < FEXP; f++) g_fnw[n * FEXP + f] = lg[f] * inv;
    }

    __half* arow = g_Ah + (size_t)n * E2D;
    #pragma unroll
    for (int i = 0; i < 4; i++) {
        arow[t + i * 128]       = __float2half(tok[i]);
        arow[DIM + t + i * 128] = __float2half(acc[i]);
    }
}

// ---------------------------------------------------------------------------
// Kernel 2: weight fp16 convert. grid (k=1024, em=16), 256 thr.
// ---------------------------------------------------------------------------
__global__ void wprep_kernel(const float* __restrict__ netW,
                             const float* __restrict__ gateW)
{
    const int k = blockIdx.x, em = blockIdx.y;
    const int mode = em >> 3, f = em & 7;
    const float* W = (mode ? gateW : netW) + ((size_t)f * E2D + k) * DIM;
    __half* dst = g_Bw + ((size_t)em * E2D + k) * DIM;
    #pragma unroll
    for (int i = 0; i < 2; i++) {
        int n = threadIdx.x + i * 256;
        dst[n] = __float2half(W[n]);
    }
}

// ---------------------------------------------------------------------------
// Kernel 3: HMMA GEMM (Round-10 config). grid (tm=128, tn=4, em=16), 256 thr,
// 2 CTAs/SM. BM=128, BN=128, BK=64, 3-stage cp.async pipeline, warp tile 64x32.
// THIS ROUND: prefetch hoisted BEFORE the MMA block — cp.async fill for
// chunk ch+2 overlaps the whole compute window of chunk ch, instead of
// starting at chunk end. Buffer (ch+2)%3 == (ch-1)%3 was last read in iter
// ch-1 (completed before this barrier), so the hoist is race-free.
// Epilogue stores use __stcs (evict-first).
// ---------------------------------------------------------------------------
#define SM_STAGE 32768   // A 16KB + B 16KB

__global__ void __launch_bounds__(256, 2)
gemm_kernel(const float* __restrict__ netb, const float* __restrict__ gateb)
{
    extern __shared__ char smraw[];
    const uint32_t sb = (smem_u32(smraw) + 1023u) & ~1023u;

    const int t    = threadIdx.x;
    const int lane = t & 31;
    const int w    = t >> 5;
    const int wm   = w >> 2;       // 0..1 -> m offset wm*64
    const int wn   = w & 3;        // 0..3 -> n offset wn*32
    const int m0g  = blockIdx.x * 128;
    const int n0g  = blockIdx.y * 128;
    const int em   = blockIdx.z;

    const char* Ag = (const char*)g_Ah + (size_t)m0g * (E2D * 2);
    const char* Bg = (const char*)g_Bw + ((size_t)em * E2D * DIM + n0g) * 2;

    auto load_stage = [&](int ch, int s) {
        const uint32_t Ab = sb + s * SM_STAGE;
        #pragma unroll
        for (int i = 0; i < 4; i++) {              // A: 128x64 fp16 = 1024 x 16B
            int idx = t + i * 256;
            int r = idx >> 3, c8 = idx & 7;
            CP_ASYNC16(Ab + r * 128 + ((c8 ^ (r & 7)) << 4),
                       Ag + (size_t)r * 2048 + ch * 128 + c8 * 16);
        }
        const uint32_t Bb = Ab + 16384;
        #pragma unroll
        for (int i = 0; i < 4; i++) {              // B: 64x128 fp16 = 1024 x 16B
            int idx = t + i * 256;
            int k = idx >> 4, g = idx & 15;
            uint32_t d = k * 256 + ((g ^ (k & 7)) << 4);
            CP_ASYNC16(Bb + d, Bg + (size_t)(ch * 64 + k) * 1024 + g * 16);
        }
        CP_COMMIT();
    };

    float acc[4][4][4];
    #pragma unroll
    for (int a = 0; a < 4; a++)
        #pragma unroll
        for (int b = 0; b < 4; b++)
            #pragma unroll
            for (int c = 0; c < 4; c++) acc[a][b][c] = 0.f;

    load_stage(0, 0);
    load_stage(1, 1);

    const int l15 = lane & 15;
    const int lhi = lane >> 4;

    for (int ch = 0; ch < 16; ch++) {
        if (ch < 15) { CP_WAIT1(); } else { CP_WAIT0(); }
        __syncthreads();

        // prefetch FIRST: next-next stage fills during this chunk's compute
        if (ch + 2 < 16) load_stage(ch + 2, (ch + 2) % 3);

        const uint32_t Ab = sb + (ch % 3) * SM_STAGE;
        const uint32_t Bb = Ab + 16384;

        #pragma unroll
        for (int ks = 0; ks < 4; ks++) {
            uint32_t af[4][4];
            #pragma unroll
            for (int mf = 0; mf < 4; mf++) {
                int row = wm * 64 + mf * 16 + l15;
                int g   = ks * 2 + lhi;
                LDSM4(af[mf], Ab + row * 128 + ((g ^ (row & 7)) << 4));
            }
            #pragma unroll
            for (int nb = 0; nb < 2; nb++) {
                uint32_t b[4];
                int k  = ks * 16 + l15;
                int n0 = wn * 32 + nb * 16 + lhi * 8;
                LDSM4T(b, Bb + k * 256 + (((n0 >> 3) ^ (k & 7)) << 4));
                #pragma unroll
                for (int mf = 0; mf < 4; mf++) {
                    MMA16816(acc[mf][nb * 2 + 0], af[mf], b[0], b[1]);
                    MMA16816(acc[mf][nb * 2 + 1], af[mf], b[2], b[3]);
                }
            }
        }
    }

    // ---- epilogue: bias + activation, streaming fp16 stores ----
    const float* bias = (em < 8) ? (netb + em * DIM) : (gateb + (em - 8) * DIM);
    __half* H = g_h + (size_t)em * N_TOK * DIM;

    #pragma unroll
    for (int mf = 0; mf < 4; mf++) {
        int m = m0g + wm * 64 + mf * 16 + (lane >> 2);
        #pragma unroll
        for (int nf = 0; nf < 4; nf++) {
            int d = n0g + wn * 32 + nf * 8 + (lane & 3) * 2;
            float b0 = __ldg(bias + d), b1 = __ldg(bias + d + 1);
            float x0 = acc[mf][nf][0] + b0;
            float x1 = acc[mf][nf][1] + b1;
            float x2 = acc[mf][nf][2] + b0;
            float x3 = acc[mf][nf][3] + b1;
            float y0, y1, y2, y3;
            if (em < 8) {
                y0 = 0.5f * x0 * (1.f + erff(x0 * 0.70710678f));
                y1 = 0.5f * x1 * (1.f + erff(x1 * 0.70710678f));
                y2 = 0.5f * x2 * (1.f + erff(x2 * 0.70710678f));
                y3 = 0.5f * x3 * (1.f + erff(x3 * 0.70710678f));
            } else {
                y0 = 1.f / (1.f + expf(-x0));
                y1 = 1.f / (1.f + expf(-x1));
                y2 = 1.f / (1.f + expf(-x2));
                y3 = 1.f / (1.f + expf(-x3));
            }
            __stcs((__half2*)&H[(size_t)m * DIM + d],       __floats2half2_rn(y0, y1));
            __stcs((__half2*)&H[(size_t)(m + 8) * DIM + d], __floats2half2_rn(y2, y3));
        }
    }
}

// ---------------------------------------------------------------------------
// Kernel 4: LN + weighted combine. warp per token. grid 2048 x 256.
// ---------------------------------------------------------------------------
__global__ void combine_kernel(const float* __restrict__ lng_,
                               const float* __restrict__ lnb_,
                               float* __restrict__ out)
{
    const int lane = threadIdx.x & 31;
    const int n = blockIdx.x * 8 + (threadIdx.x >> 5);

    float op[16], og[16];
    #pragma unroll
    for (int j = 0; j < 16; j++) { op[j] = 0.f; og[j] = 0.f; }

    #pragma unroll
    for (int f = 0; f < FEXP; f++) {
        const float fnw = g_fnw[n * FEXP + f];

        const uint4* hp = (const uint4*)(g_h + ((size_t)f * N_TOK + n) * DIM);
        float x[16];
        float s = 0.f, s2 = 0.f;
        #pragma unroll
        for (int c = 0; c < 2; c++) {
            uint4 raw = __ldcs(hp + c * 32 + lane);
            const __half2* h2 = (const __half2*)&raw;
            #pragma unroll
            for (int q = 0; q < 4; q++) {
                float2 v = __half22float2(h2[q]);
                x[c*8 + q*2 + 0] = v.x;
                x[c*8 + q*2 + 1] = v.y;
                s += v.x + v.y;
                s2 = fmaf(v.x, v.x, s2); s2 = fmaf(v.y, v.y, s2);
            }
        }
        #pragma unroll
        for (int o = 16; o; o >>= 1) {
            s  += __shfl_xor_sync(0xffffffffu, s,  o);
            s2 += __shfl_xor_sync(0xffffffffu, s2, o);
        }
        float mu = s * (1.f / DIM);
        float var = s2 * (1.f / DIM) - mu * mu;
        float rs = rsqrtf(fmaxf(var, 0.f) + LN_EPS);

        #pragma unroll
        for (int c = 0; c < 2; c++) {
            int d = (c * 32 + lane) * 8;
            #pragma unroll
            for (int q = 0; q < 2; q++) {
                float4 gv = *(const float4*)&lng_[f * DIM + d + q * 4];
                float4 bv = *(const float4*)&lnb_[f * DIM + d + q * 4];
                int j = c * 8 + q * 4;
                op[j+0] = fmaf(fnw, (x[j+0] - mu) * rs * gv.x + bv.x, op[j+0]);
                op[j+1] = fmaf(fnw, (x[j+1] - mu) * rs * gv.y + bv.y, op[j+1]);
                op[j+2] = fmaf(fnw, (x[j+2] - mu) * rs * gv.z + bv.z, op[j+2]);
                op[j+3] = fmaf(fnw, (x[j+3] - mu) * rs * gv.w + bv.w, op[j+3]);
            }
        }

        const uint4* gp = (const uint4*)(g_h + ((size_t)(8 + f) * N_TOK + n) * DIM);
        #pragma unroll
        for (int c = 0; c < 2; c++) {
            uint4 raw = __ldcs(gp + c * 32 + lane);
            const __half2* h2 = (const __half2*)&raw;
            #pragma unroll
            for (int q = 0; q < 4; q++) {
                float2 v = __half22float2(h2[q]);
                og[c*8 + q*2 + 0] = fmaf(fnw, v.x, og[c*8 + q*2 + 0]);
                og[c*8 + q*2 + 1] = fmaf(fnw, v.y, og[c*8 + q*2 + 1]);
            }
        }
    }

    #pragma unroll
    for (int c = 0; c < 2; c++) {
        int d = (c * 32 + lane) * 8;
        *(float4*)&out[(size_t)n * DIM + d] =
            make_float4(op[c*8+0], op[c*8+1], op[c*8+2], op[c*8+3]);
        *(float4*)&out[(size_t)n * DIM + d + 4] =
            make_float4(op[c*8+4], op[c*8+5], op[c*8+6], op[c*8+7]);
        *(float4*)&out[((size_t)N_TOK + n) * DIM + d] =
            make_float4(og[c*8+0], og[c*8+1], og[c*8+2], og[c*8+3]);
        *(float4*)&out[((size_t)N_TOK + n) * DIM + d + 4] =
            make_float4(og[c*8+4], og[c*8+5], og[c*8+6], og[c*8+7]);
    }
}

// ---------------------------------------------------------------------------
extern "C" void kernel_launch(void* const* d_in, const int* in_sizes, int n_in,
                              void* d_out, int out_size) {
    const float* token  = (const float*)d_in[0];
    const float* routed = (const float*)d_in[1];
    const float* sim    = (const float*)d_in[2];
    const float* selW   = (const float*)d_in[3];
    const float* selb   = (const float*)d_in[4];
    const float* netW   = (const float*)d_in[5];
    const float* netb   = (const float*)d_in[6];
    const float* lng    = (const float*)d_in[7];
    const float* lnb    = (const float*)d_in[8];
    const float* gateW  = (const float*)d_in[9];
    const float* gateb  = (const float*)d_in[10];
    float* out = (float*)d_out;

    const int smem_bytes = 3 * SM_STAGE + 1024;   // 99328 -> 2 CTAs/SM
    cudaFuncSetAttribute(gemm_kernel,
                         cudaFuncAttributeMaxDynamicSharedMemorySize, smem_bytes);

    prep_kernel<<<N_TOK, 128>>>(token, routed, sim, selW, selb);
    wprep_kernel<<<dim3(E2D, 16), 256>>>(netW, gateW);
    gemm_kernel<<<dim3(128, 4, 16), 256, smem_bytes>>>(netb, gateb);
    combine_kernel<<<N_TOK / 8, 256>>>(lng, lnb, out);
}

// round 15
// speedup vs baseline: 1.0228x; 1.0228x over previous
#include <cuda_runtime.h>
#include <cuda_fp16.h>
#include <math.h>
#include <stdint.h>

#define N_TOK 16384
#define KNN   32
#define DIM   512
#define FEXP  8
#define E2D   1024
#define LN_EPS 1e-5f

// ---------------- device scratch (allocation-free rule) ----------------
__device__ float  g_fnw[N_TOK * FEXP];
__device__ __align__(16) __half g_Ah[(size_t)N_TOK * E2D];           // inp fp16 [N,1024]
__device__ __align__(16) __half g_Bw[(size_t)16 * E2D * DIM];        // [em][k][d] fp16
__device__ __align__(16) __half g_h [(size_t)16 * N_TOK * DIM];      // activated h per em (fp16)

__device__ __forceinline__ unsigned smem_u32(const void* p) {
    return (unsigned)__cvta_generic_to_shared(p);
}
#define CP_ASYNC16(dst, src) asm volatile("cp.async.cg.shared.global [%0], [%1], 16;" :: "r"(dst), "l"(src))
#define CP_COMMIT() asm volatile("cp.async.commit_group;" ::: "memory")
#define CP_WAIT0()  asm volatile("cp.async.wait_group 0;" ::: "memory")
#define CP_WAIT1()  asm volatile("cp.async.wait_group 1;" ::: "memory")

#define LDSM4(r, addr) \
    asm volatile("ldmatrix.sync.aligned.m8n8.x4.shared.b16 {%0,%1,%2,%3}, [%4];" \
        : "=r"((r)[0]), "=r"((r)[1]), "=r"((r)[2]), "=r"((r)[3]) : "r"(addr))
#define LDSM4T(r, addr) \
    asm volatile("ldmatrix.sync.aligned.m8n8.x4.trans.shared.b16 {%0,%1,%2,%3}, [%4];" \
        : "=r"((r)[0]), "=r"((r)[1]), "=r"((r)[2]), "=r"((r)[3]) : "r"(addr))
#define MMA16816(d, a, b0, b1) \
    asm volatile("mma.sync.aligned.m16n8k16.row.col.f32.f16.f16.f32 " \
        "{%0,%1,%2,%3}, {%4,%5,%6,%7}, {%8,%9}, {%0,%1,%2,%3};" \
        : "+f"((d)[0]), "+f"((d)[1]), "+f"((d)[2]), "+f"((d)[3]) \
        : "r"((a)[0]), "r"((a)[1]), "r"((a)[2]), "r"((a)[3]), "r"(b0), "r"(b1))

// ---------------------------------------------------------------------------
// Kernel 1: per-row prep -> fnw + fp16 inp rows (R12 champion version).
// ---------------------------------------------------------------------------
__global__ void prep_kernel(const float* __restrict__ token,
                            const float* __restrict__ routed,
                            const float* __restrict__ sim,
                            const float* __restrict__ selW,
                            const float* __restrict__ selb)
{
    const int n = blockIdx.x;
    const int t = threadIdx.x;           // 0..127

    __shared__ float wsm[KNN];
    __shared__ float partsm[4 * FEXP];

    if (t < KNN) {
        float s = sim[n * KNN + t];
        float m = s;
        #pragma unroll
        for (int o = 16; o; o >>= 1) m = fmaxf(m, __shfl_xor_sync(0xffffffffu, m, o));
        float e = expf(s - m);
        float sum = e;
        #pragma unroll
        for (int o = 16; o; o >>= 1) sum += __shfl_xor_sync(0xffffffffu, sum, o);
        wsm[t] = e / sum;
    }
    __syncthreads();

    float tok[4], acc[4];
    #pragma unroll
    for (int i = 0; i < 4; i++) {
        tok[i] = __ldcs(token + (size_t)n * DIM + t + i * 128);
        acc[i] = 0.f;
    }
    const float* rbase = routed + (size_t)n * KNN * DIM + t;
    #pragma unroll 4
    for (int k = 0; k < KNN; k++) {
        float wk = wsm[k];
        #pragma unroll
        for (int i = 0; i < 4; i++)
            acc[i] = fmaf(wk, __ldcs(rbase + (size_t)k * DIM + i * 128), acc[i]);
    }

    float part[FEXP];
    #pragma unroll
    for (int f = 0; f < FEXP; f++) part[f] = 0.f;
    #pragma unroll
    for (int i = 0; i < 4; i++) {
        int d = t + i * 128;
        #pragma unroll
        for (int f = 0; f < FEXP; f++)
            part[f] = fmaf(tok[i], selW[d * FEXP + f], part[f]);
    }
    #pragma unroll
    for (int f = 0; f < FEXP; f++) {
        float v = part[f];
        #pragma unroll
        for (int o = 16; o; o >>= 1) v += __shfl_xor_sync(0xffffffffu, v, o);
        if ((t & 31) == 0) partsm[(t >> 5) * FEXP + f] = v;
    }
    __syncthreads();
    if (t == 0) {
        float lg[FEXP];
        float m = -1e30f;
        #pragma unroll
        for (int f = 0; f < FEXP; f++) {
            lg[f] = selb[f] + partsm[f] + partsm[FEXP + f]
                  + partsm[2 * FEXP + f] + partsm[3 * FEXP + f];
            m = fmaxf(m, lg[f]);
        }
        float s = 0.f;
        #pragma unroll
        for (int f = 0; f < FEXP; f++) { lg[f] = expf(lg[f] - m); s += lg[f]; }
        float inv = 1.f / s;
        #pragma unroll
        for (int f = 0; f < FEXP; f++) g_fnw[n * FEXP + f] = lg[f] * inv;
    }

    __half* arow = g_Ah + (size_t)n * E2D;
    #pragma unroll
    for (int i = 0; i < 4; i++) {
        arow[t + i * 128]       = __float2half(tok[i]);
        arow[DIM + t + i * 128] = __float2half(acc[i]);
    }
}

// ---------------------------------------------------------------------------
// Kernel 2: weight fp16 convert. grid (k=1024, em=16), 256 thr.
// ---------------------------------------------------------------------------
__global__ void wprep_kernel(const float* __restrict__ netW,
                             const float* __restrict__ gateW)
{
    const int k = blockIdx.x, em = blockIdx.y;
    const int mode = em >> 3, f = em & 7;
    const float* W = (mode ? gateW : netW) + ((size_t)f * E2D + k) * DIM;
    __half* dst = g_Bw + ((size_t)em * E2D + k) * DIM;
    #pragma unroll
    for (int i = 0; i < 2; i++) {
        int n = threadIdx.x + i * 256;
        dst[n] = __float2half(W[n]);
    }
}

// ---------------------------------------------------------------------------
// Kernel 3: HMMA GEMM (Round-10/12 champion, verbatim).
// grid (tm=128, tn=4, em=16), 256 thr, 2 CTAs/SM.
// BM=128, BN=128, BK=64, 3-stage cp.async pipeline, warp tile 64x32.
// ---------------------------------------------------------------------------
#define SM_STAGE 32768   // A 16KB + B 16KB

__global__ void __launch_bounds__(256, 2)
gemm_kernel(const float* __restrict__ netb, const float* __restrict__ gateb)
{
    extern __shared__ char smraw[];
    const uint32_t sb = (smem_u32(smraw) + 1023u) & ~1023u;

    const int t    = threadIdx.x;
    const int lane = t & 31;
    const int w    = t >> 5;
    const int wm   = w >> 2;       // 0..1 -> m offset wm*64
    const int wn   = w & 3;        // 0..3 -> n offset wn*32
    const int m0g  = blockIdx.x * 128;
    const int n0g  = blockIdx.y * 128;
    const int em   = blockIdx.z;

    const char* Ag = (const char*)g_Ah + (size_t)m0g * (E2D * 2);
    const char* Bg = (const char*)g_Bw + ((size_t)em * E2D * DIM + n0g) * 2;

    auto load_stage = [&](int ch, int s) {
        const uint32_t Ab = sb + s * SM_STAGE;
        #pragma unroll
        for (int i = 0; i < 4; i++) {              // A: 128x64 fp16 = 1024 x 16B
            int idx = t + i * 256;
            int r = idx >> 3, c8 = idx & 7;
            CP_ASYNC16(Ab + r * 128 + ((c8 ^ (r & 7)) << 4),
                       Ag + (size_t)r * 2048 + ch * 128 + c8 * 16);
        }
        const uint32_t Bb = Ab + 16384;
        #pragma unroll
        for (int i = 0; i < 4; i++) {              // B: 64x128 fp16 = 1024 x 16B
            int idx = t + i * 256;
            int k = idx >> 4, g = idx & 15;
            uint32_t d = k * 256 + ((g ^ (k & 7)) << 4);
            CP_ASYNC16(Bb + d, Bg + (size_t)(ch * 64 + k) * 1024 + g * 16);
        }
        CP_COMMIT();
    };

    float acc[4][4][4];
    #pragma unroll
    for (int a = 0; a < 4; a++)
        #pragma unroll
        for (int b = 0; b < 4; b++)
            #pragma unroll
            for (int c = 0; c < 4; c++) acc[a][b][c] = 0.f;

    load_stage(0, 0);
    load_stage(1, 1);

    const int l15 = lane & 15;
    const int lhi = lane >> 4;

    for (int ch = 0; ch < 16; ch++) {
        if (ch < 15) { CP_WAIT1(); } else { CP_WAIT0(); }
        __syncthreads();

        const uint32_t Ab = sb + (ch % 3) * SM_STAGE;
        const uint32_t Bb = Ab + 16384;

        #pragma unroll
        for (int ks = 0; ks < 4; ks++) {
            uint32_t af[4][4];
            #pragma unroll
            for (int mf = 0; mf < 4; mf++) {
                int row = wm * 64 + mf * 16 + l15;
                int g   = ks * 2 + lhi;
                LDSM4(af[mf], Ab + row * 128 + ((g ^ (row & 7)) << 4));
            }
            #pragma unroll
            for (int nb = 0; nb < 2; nb++) {
                uint32_t b[4];
                int k  = ks * 16 + l15;
                int n0 = wn * 32 + nb * 16 + lhi * 8;
                LDSM4T(b, Bb + k * 256 + (((n0 >> 3) ^ (k & 7)) << 4));
                #pragma unroll
                for (int mf = 0; mf < 4; mf++) {
                    MMA16816(acc[mf][nb * 2 + 0], af[mf], b[0], b[1]);
                    MMA16816(acc[mf][nb * 2 + 1], af[mf], b[2], b[3]);
                }
            }
        }
        if (ch + 2 < 16) load_stage(ch + 2, (ch + 2) % 3);
    }

    // ---- epilogue: bias + activation, store fp16 ----
    const float* bias = (em < 8) ? (netb + em * DIM) : (gateb + (em - 8) * DIM);
    __half* H = g_h + (size_t)em * N_TOK * DIM;

    #pragma unroll
    for (int mf = 0; mf < 4; mf++) {
        int m = m0g + wm * 64 + mf * 16 + (lane >> 2);
        #pragma unroll
        for (int nf = 0; nf < 4; nf++) {
            int d = n0g + wn * 32 + nf * 8 + (lane & 3) * 2;
            float b0 = __ldg(bias + d), b1 = __ldg(bias + d + 1);
            float x0 = acc[mf][nf][0] + b0;
            float x1 = acc[mf][nf][1] + b1;
            float x2 = acc[mf][nf][2] + b0;
            float x3 = acc[mf][nf][3] + b1;
            float y0, y1, y2, y3;
            if (em < 8) {
                y0 = 0.5f * x0 * (1.f + erff(x0 * 0.70710678f));
                y1 = 0.5f * x1 * (1.f + erff(x1 * 0.70710678f));
                y2 = 0.5f * x2 * (1.f + erff(x2 * 0.70710678f));
                y3 = 0.5f * x3 * (1.f + erff(x3 * 0.70710678f));
            } else {
                y0 = 1.f / (1.f + expf(-x0));
                y1 = 1.f / (1.f + expf(-x1));
                y2 = 1.f / (1.f + expf(-x2));
                y3 = 1.f / (1.f + expf(-x3));
            }
            *(__half2*)&H[(size_t)m * DIM + d]       = __floats2half2_rn(y0, y1);
            *(__half2*)&H[(size_t)(m + 8) * DIM + d] = __floats2half2_rn(y2, y3);
        }
    }
}

// ---------------------------------------------------------------------------
// Kernel 4: LN + weighted combine. warp per token. grid 2048 x 256.
// R13 version: f-loop fully unrolled, __ldcs on single-use g_h reads
// (measured 78.4us vs 80.6us for the non-unrolled variant).
// ---------------------------------------------------------------------------
__global__ void combine_kernel(const float* __restrict__ lng_,
                               const float* __restrict__ lnb_,
                               float* __restrict__ out)
{
    const int lane = threadIdx.x & 31;
    const int n = blockIdx.x * 8 + (threadIdx.x >> 5);

    float op[16], og[16];
    #pragma unroll
    for (int j = 0; j < 16; j++) { op[j] = 0.f; og[j] = 0.f; }

    #pragma unroll
    for (int f = 0; f < FEXP; f++) {
        const float fnw = g_fnw[n * FEXP + f];

        const uint4* hp = (const uint4*)(g_h + ((size_t)f * N_TOK + n) * DIM);
        float x[16];
        float s = 0.f, s2 = 0.f;
        #pragma unroll
        for (int c = 0; c < 2; c++) {
            uint4 raw = __ldcs(hp + c * 32 + lane);
            const __half2* h2 = (const __half2*)&raw;
            #pragma unroll
            for (int q = 0; q < 4; q++) {
                float2 v = __half22float2(h2[q]);
                x[c*8 + q*2 + 0] = v.x;
                x[c*8 + q*2 + 1] = v.y;
                s += v.x + v.y;
                s2 = fmaf(v.x, v.x, s2); s2 = fmaf(v.y, v.y, s2);
            }
        }
        #pragma unroll
        for (int o = 16; o; o >>= 1) {
            s  += __shfl_xor_sync(0xffffffffu, s,  o);
            s2 += __shfl_xor_sync(0xffffffffu, s2, o);
        }
        float mu = s * (1.f / DIM);
        float var = s2 * (1.f / DIM) - mu * mu;
        float rs = rsqrtf(fmaxf(var, 0.f) + LN_EPS);

        #pragma unroll
        for (int c = 0; c < 2; c++) {
            int d = (c * 32 + lane) * 8;
            #pragma unroll
            for (int q = 0; q < 2; q++) {
                float4 gv = *(const float4*)&lng_[f * DIM + d + q * 4];
                float4 bv = *(const float4*)&lnb_[f * DIM + d + q * 4];
                int j = c * 8 + q * 4;
                op[j+0] = fmaf(fnw, (x[j+0] - mu) * rs * gv.x + bv.x, op[j+0]);
                op[j+1] = fmaf(fnw, (x[j+1] - mu) * rs * gv.y + bv.y, op[j+1]);
                op[j+2] = fmaf(fnw, (x[j+2] - mu) * rs * gv.z + bv.z, op[j+2]);
                op[j+3] = fmaf(fnw, (x[j+3] - mu) * rs * gv.w + bv.w, op[j+3]);
            }
        }

        const uint4* gp = (const uint4*)(g_h + ((size_t)(8 + f) * N_TOK + n) * DIM);
        #pragma unroll
        for (int c = 0; c < 2; c++) {
            uint4 raw = __ldcs(gp + c * 32 + lane);
            const __half2* h2 = (const __half2*)&raw;
            #pragma unroll
            for (int q = 0; q < 4; q++) {
                float2 v = __half22float2(h2[q]);
                og[c*8 + q*2 + 0] = fmaf(fnw, v.x, og[c*8 + q*2 + 0]);
                og[c*8 + q*2 + 1] = fmaf(fnw, v.y, og[c*8 + q*2 + 1]);
            }
        }
    }

    #pragma unroll
    for (int c = 0; c < 2; c++) {
        int d = (c * 32 + lane) * 8;
        *(float4*)&out[(size_t)n * DIM + d] =
            make_float4(op[c*8+0], op[c*8+1], op[c*8+2], op[c*8+3]);
        *(float4*)&out[(size_t)n * DIM + d + 4] =
            make_float4(op[c*8+4], op[c*8+5], op[c*8+6], op[c*8+7]);
        *(float4*)&out[((size_t)N_TOK + n) * DIM + d] =
            make_float4(og[c*8+0], og[c*8+1], og[c*8+2], og[c*8+3]);
        *(float4*)&out[((size_t)N_TOK + n) * DIM + d + 4] =
            make_float4(og[c*8+4], og[c*8+5], og[c*8+6], og[c*8+7]);
    }
}

// ---------------------------------------------------------------------------
extern "C" void kernel_launch(void* const* d_in, const int* in_sizes, int n_in,
                              void* d_out, int out_size) {
    const float* token  = (const float*)d_in[0];
    const float* routed = (const float*)d_in[1];
    const float* sim    = (const float*)d_in[2];
    const float* selW   = (const float*)d_in[3];
    const float* selb   = (const float*)d_in[4];
    const float* netW   = (const float*)d_in[5];
    const float* netb   = (const float*)d_in[6];
    const float* lng    = (const float*)d_in[7];
    const float* lnb    = (const float*)d_in[8];
    const float* gateW  = (const float*)d_in[9];
    const float* gateb  = (const float*)d_in[10];
    float* out = (float*)d_out;

    const int smem_bytes = 3 * SM_STAGE + 1024;   // 99328 -> 2 CTAs/SM
    cudaFuncSetAttribute(gemm_kernel,
                         cudaFuncAttributeMaxDynamicSharedMemorySize, smem_bytes);

    prep_kernel<<<N_TOK, 128>>>(token, routed, sim, selW, selb);
    wprep_kernel<<<dim3(E2D, 16), 256>>>(netW, gateW);
    gemm_kernel<<<dim3(128, 4, 16), 256, smem_bytes>>>(netb, gateb);
    combine_kernel<<<N_TOK / 8, 256>>>(lng, lnb, out);
}

// round 16
// speedup vs baseline: 1.0288x; 1.0059x over previous
#include <cuda_runtime.h>
#include <cuda_fp16.h>
#include <math.h>
#include <stdint.h>

#define N_TOK 16384
#define KNN   32
#define DIM   512
#define FEXP  8
#define E2D   1024
#define LN_EPS 1e-5f

#define W_ELEMS ((size_t)FEXP * E2D * DIM)        // 4,194,304 floats per tensor
#define CONV_BLOCKS 4096                           // 2*W_ELEMS / 2048

// ---------------- device scratch (allocation-free rule) ----------------
__device__ float  g_fnw[N_TOK * FEXP];
__device__ __align__(16) __half g_Ah[(size_t)N_TOK * E2D];           // inp fp16 [N,1024]
__device__ __align__(16) __half g_Bw[(size_t)16 * E2D * DIM];        // [em][k][d] fp16
__device__ __align__(16) __half g_h [(size_t)16 * N_TOK * DIM];      // activated h per em (fp16)

__device__ __forceinline__ unsigned smem_u32(const void* p) {
    return (unsigned)__cvta_generic_to_shared(p);
}
#define CP_ASYNC16(dst, src) asm volatile("cp.async.cg.shared.global [%0], [%1], 16;" :: "r"(dst), "l"(src))
#define CP_COMMIT() asm volatile("cp.async.commit_group;" ::: "memory")
#define CP_WAIT0()  asm volatile("cp.async.wait_group 0;" ::: "memory")
#define CP_WAIT1()  asm volatile("cp.async.wait_group 1;" ::: "memory")

#define LDSM4(r, addr) \
    asm volatile("ldmatrix.sync.aligned.m8n8.x4.shared.b16 {%0,%1,%2,%3}, [%4];" \
        : "=r"((r)[0]), "=r"((r)[1]), "=r"((r)[2]), "=r"((r)[3]) : "r"(addr))
#define LDSM4T(r, addr) \
    asm volatile("ldmatrix.sync.aligned.m8n8.x4.trans.shared.b16 {%0,%1,%2,%3}, [%4];" \
        : "=r"((r)[0]), "=r"((r)[1]), "=r"((r)[2]), "=r"((r)[3]) : "r"(addr))
#define MMA16816(d, a, b0, b1) \
    asm volatile("mma.sync.aligned.m16n8k16.row.col.f32.f16.f16.f32 " \
        "{%0,%1,%2,%3}, {%4,%5,%6,%7}, {%8,%9}, {%0,%1,%2,%3};" \
        : "+f"((d)[0]), "+f"((d)[1]), "+f"((d)[2]), "+f"((d)[3]) \
        : "r"((a)[0]), "r"((a)[1]), "r"((a)[2]), "r"((a)[3]), "r"(b0), "r"(b1))

// ---------------------------------------------------------------------------
// Kernel 1 (merged): blocks [0,16384) = per-row prep (R12 champion body);
// blocks [16384, 16384+4096) = linear W fp32->fp16 conversion.
// g_Bw layout [em][k][d] == flat [f][k][d] of netW (em<8) / gateW (em>=8),
// so conversion is two straight streams; overlaps inside prep's DRAM window.
// ---------------------------------------------------------------------------
__global__ void prep_kernel(const float* __restrict__ token,
                            const float* __restrict__ routed,
                            const float* __restrict__ sim,
                            const float* __restrict__ selW,
                            const float* __restrict__ selb,
                            const float* __restrict__ netW,
                            const float* __restrict__ gateW)
{
    const int t = threadIdx.x;           // 0..127

    if (blockIdx.x >= N_TOK) {
        // ---- weight conversion: 2048 elements per block, 16 per thread ----
        const size_t cb   = blockIdx.x - N_TOK;          // 0..4095
        const size_t idx0 = cb * 2048 + (size_t)t * 16;
        const float* src = (idx0 < W_ELEMS) ? (netW + idx0) : (gateW + (idx0 - W_ELEMS));
        __half* dst = g_Bw + idx0;
        #pragma unroll
        for (int q = 0; q < 4; q++) {
            float4 v = __ldcs((const float4*)(src + q * 4));
            __half2 lo = __floats2half2_rn(v.x, v.y);
            __half2 hi = __floats2half2_rn(v.z, v.w);
            *(__half2*)(dst + q * 4)     = lo;
            *(__half2*)(dst + q * 4 + 2) = hi;
        }
        return;
    }

    const int n = blockIdx.x;

    __shared__ float wsm[KNN];
    __shared__ float partsm[4 * FEXP];

    if (t < KNN) {
        float s = sim[n * KNN + t];
        float m = s;
        #pragma unroll
        for (int o = 16; o; o >>= 1) m = fmaxf(m, __shfl_xor_sync(0xffffffffu, m, o));
        float e = expf(s - m);
        float sum = e;
        #pragma unroll
        for (int o = 16; o; o >>= 1) sum += __shfl_xor_sync(0xffffffffu, sum, o);
        wsm[t] = e / sum;
    }
    __syncthreads();

    float tok[4], acc[4];
    #pragma unroll
    for (int i = 0; i < 4; i++) {
        tok[i] = __ldcs(token + (size_t)n * DIM + t + i * 128);
        acc[i] = 0.f;
    }
    const float* rbase = routed + (size_t)n * KNN * DIM + t;
    #pragma unroll 4
    for (int k = 0; k < KNN; k++) {
        float wk = wsm[k];
        #pragma unroll
        for (int i = 0; i < 4; i++)
            acc[i] = fmaf(wk, __ldcs(rbase + (size_t)k * DIM + i * 128), acc[i]);
    }

    float part[FEXP];
    #pragma unroll
    for (int f = 0; f < FEXP; f++) part[f] = 0.f;
    #pragma unroll
    for (int i = 0; i < 4; i++) {
        int d = t + i * 128;
        #pragma unroll
        for (int f = 0; f < FEXP; f++)
            part[f] = fmaf(tok[i], selW[d * FEXP + f], part[f]);
    }
    #pragma unroll
    for (int f = 0; f < FEXP; f++) {
        float v = part[f];
        #pragma unroll
        for (int o = 16; o; o >>= 1) v += __shfl_xor_sync(0xffffffffu, v, o);
        if ((t & 31) == 0) partsm[(t >> 5) * FEXP + f] = v;
    }
    __syncthreads();
    if (t == 0) {
        float lg[FEXP];
        float m = -1e30f;
        #pragma unroll
        for (int f = 0; f < FEXP; f++) {
            lg[f] = selb[f] + partsm[f] + partsm[FEXP + f]
                  + partsm[2 * FEXP + f] + partsm[3 * FEXP + f];
            m = fmaxf(m, lg[f]);
        }
        float s = 0.f;
        #pragma unroll
        for (int f = 0; f < FEXP; f++) { lg[f] = expf(lg[f] - m); s += lg[f]; }
        float inv = 1.f / s;
        #pragma unroll
        for (int f = 0; f < FEXP; f++) g_fnw[n * FEXP + f] = lg[f] * inv;
    }

    __half* arow = g_Ah + (size_t)n * E2D;
    #pragma unroll
    for (int i = 0; i < 4; i++) {
        arow[t + i * 128]       = __float2half(tok[i]);
        arow[DIM + t + i * 128] = __float2half(acc[i]);
    }
}

// ---------------------------------------------------------------------------
// Kernel 2: HMMA GEMM (Round-10/12 champion, verbatim).
// grid (tm=128, tn=4, em=16), 256 thr, 2 CTAs/SM.
// BM=128, BN=128, BK=64, 3-stage cp.async pipeline, warp tile 64x32.
// ---------------------------------------------------------------------------
#define SM_STAGE 32768   // A 16KB + B 16KB

__global__ void __launch_bounds__(256, 2)
gemm_kernel(const float* __restrict__ netb, const float* __restrict__ gateb)
{
    extern __shared__ char smraw[];
    const uint32_t sb = (smem_u32(smraw) + 1023u) & ~1023u;

    const int t    = threadIdx.x;
    const int lane = t & 31;
    const int w    = t >> 5;
    const int wm   = w >> 2;       // 0..1 -> m offset wm*64
    const int wn   = w & 3;        // 0..3 -> n offset wn*32
    const int m0g  = blockIdx.x * 128;
    const int n0g  = blockIdx.y * 128;
    const int em   = blockIdx.z;

    const char* Ag = (const char*)g_Ah + (size_t)m0g * (E2D * 2);
    const char* Bg = (const char*)g_Bw + ((size_t)em * E2D * DIM + n0g) * 2;

    auto load_stage = [&](int ch, int s) {
        const uint32_t Ab = sb + s * SM_STAGE;
        #pragma unroll
        for (int i = 0; i < 4; i++) {              // A: 128x64 fp16 = 1024 x 16B
            int idx = t + i * 256;
            int r = idx >> 3, c8 = idx & 7;
            CP_ASYNC16(Ab + r * 128 + ((c8 ^ (r & 7)) << 4),
                       Ag + (size_t)r * 2048 + ch * 128 + c8 * 16);
        }
        const uint32_t Bb = Ab + 16384;
        #pragma unroll
        for (int i = 0; i < 4; i++) {              // B: 64x128 fp16 = 1024 x 16B
            int idx = t + i * 256;
            int k = idx >> 4, g = idx & 15;
            uint32_t d = k * 256 + ((g ^ (k & 7)) << 4);
            CP_ASYNC16(Bb + d, Bg + (size_t)(ch * 64 + k) * 1024 + g * 16);
        }
        CP_COMMIT();
    };

    float acc[4][4][4];
    #pragma unroll
    for (int a = 0; a < 4; a++)
        #pragma unroll
        for (int b = 0; b < 4; b++)
            #pragma unroll
            for (int c = 0; c < 4; c++) acc[a][b][c] = 0.f;

    load_stage(0, 0);
    load_stage(1, 1);

    const int l15 = lane & 15;
    const int lhi = lane >> 4;

    for (int ch = 0; ch < 16; ch++) {
        if (ch < 15) { CP_WAIT1(); } else { CP_WAIT0(); }
        __syncthreads();

        const uint32_t Ab = sb + (ch % 3) * SM_STAGE;
        const uint32_t Bb = Ab + 16384;

        #pragma unroll
        for (int ks = 0; ks < 4; ks++) {
            uint32_t af[4][4];
            #pragma unroll
            for (int mf = 0; mf < 4; mf++) {
                int row = wm * 64 + mf * 16 + l15;
                int g   = ks * 2 + lhi;
                LDSM4(af[mf], Ab + row * 128 + ((g ^ (row & 7)) << 4));
            }
            #pragma unroll
            for (int nb = 0; nb < 2; nb++) {
                uint32_t b[4];
                int k  = ks * 16 + l15;
                int n0 = wn * 32 + nb * 16 + lhi * 8;
                LDSM4T(b, Bb + k * 256 + (((n0 >> 3) ^ (k & 7)) << 4));
                #pragma unroll
                for (int mf = 0; mf < 4; mf++) {
                    MMA16816(acc[mf][nb * 2 + 0], af[mf], b[0], b[1]);
                    MMA16816(acc[mf][nb * 2 + 1], af[mf], b[2], b[3]);
                }
            }
        }
        if (ch + 2 < 16) load_stage(ch + 2, (ch + 2) % 3);
    }

    // ---- epilogue: bias + activation, store fp16 ----
    const float* bias = (em < 8) ? (netb + em * DIM) : (gateb + (em - 8) * DIM);
    __half* H = g_h + (size_t)em * N_TOK * DIM;

    #pragma unroll
    for (int mf = 0; mf < 4; mf++) {
        int m = m0g + wm * 64 + mf * 16 + (lane >> 2);
        #pragma unroll
        for (int nf = 0; nf < 4; nf++) {
            int d = n0g + wn * 32 + nf * 8 + (lane & 3) * 2;
            float b0 = __ldg(bias + d), b1 = __ldg(bias + d + 1);
            float x0 = acc[mf][nf][0] + b0;
            float x1 = acc[mf][nf][1] + b1;
            float x2 = acc[mf][nf][2] + b0;
            float x3 = acc[mf][nf][3] + b1;
            float y0, y1, y2, y3;
            if (em < 8) {
                y0 = 0.5f * x0 * (1.f + erff(x0 * 0.70710678f));
                y1 = 0.5f * x1 * (1.f + erff(x1 * 0.70710678f));
                y2 = 0.5f * x2 * (1.f + erff(x2 * 0.70710678f));
                y3 = 0.5f * x3 * (1.f + erff(x3 * 0.70710678f));
            } else {
                y0 = 1.f / (1.f + expf(-x0));
                y1 = 1.f / (1.f + expf(-x1));
                y2 = 1.f / (1.f + expf(-x2));
                y3 = 1.f / (1.f + expf(-x3));
            }
            *(__half2*)&H[(size_t)m * DIM + d]       = __floats2half2_rn(y0, y1);
            *(__half2*)&H[(size_t)(m + 8) * DIM + d] = __floats2half2_rn(y2, y3);
        }
    }
}

// ---------------------------------------------------------------------------
// Kernel 3: LN + weighted combine. warp per token. grid 2048 x 256.
// R13/R15 version: f-loop fully unrolled, __ldcs on single-use g_h reads.
// ---------------------------------------------------------------------------
__global__ void combine_kernel(const float* __restrict__ lng_,
                               const float* __restrict__ lnb_,
                               float* __restrict__ out)
{
    const int lane = threadIdx.x & 31;
    const int n = blockIdx.x * 8 + (threadIdx.x >> 5);

    float op[16], og[16];
    #pragma unroll
    for (int j = 0; j < 16; j++) { op[j] = 0.f; og[j] = 0.f; }

    #pragma unroll
    for (int f = 0; f < FEXP; f++) {
        const float fnw = g_fnw[n * FEXP + f];

        const uint4* hp = (const uint4*)(g_h + ((size_t)f * N_TOK + n) * DIM);
        float x[16];
        float s = 0.f, s2 = 0.f;
        #pragma unroll
        for (int c = 0; c < 2; c++) {
            uint4 raw = __ldcs(hp + c * 32 + lane);
            const __half2* h2 = (const __half2*)&raw;
            #pragma unroll
            for (int q = 0; q < 4; q++) {
                float2 v = __half22float2(h2[q]);
                x[c*8 + q*2 + 0] = v.x;
                x[c*8 + q*2 + 1] = v.y;
                s += v.x + v.y;
                s2 = fmaf(v.x, v.x, s2); s2 = fmaf(v.y, v.y, s2);
            }
        }
        #pragma unroll
        for (int o = 16; o; o >>= 1) {
            s  += __shfl_xor_sync(0xffffffffu, s,  o);
            s2 += __shfl_xor_sync(0xffffffffu, s2, o);
        }
        float mu = s * (1.f / DIM);
        float var = s2 * (1.f / DIM) - mu * mu;
        float rs = rsqrtf(fmaxf(var, 0.f) + LN_EPS);

        #pragma unroll
        for (int c = 0; c < 2; c++) {
            int d = (c * 32 + lane) * 8;
            #pragma unroll
            for (int q = 0; q < 2; q++) {
                float4 gv = *(const float4*)&lng_[f * DIM + d + q * 4];
                float4 bv = *(const float4*)&lnb_[f * DIM + d + q * 4];
                int j = c * 8 + q * 4;
                op[j+0] = fmaf(fnw, (x[j+0] - mu) * rs * gv.x + bv.x, op[j+0]);
                op[j+1] = fmaf(fnw, (x[j+1] - mu) * rs * gv.y + bv.y, op[j+1]);
                op[j+2] = fmaf(fnw, (x[j+2] - mu) * rs * gv.z + bv.z, op[j+2]);
                op[j+3] = fmaf(fnw, (x[j+3] - mu) * rs * gv.w + bv.w, op[j+3]);
            }
        }

        const uint4* gp = (const uint4*)(g_h + ((size_t)(8 + f) * N_TOK + n) * DIM);
        #pragma unroll
        for (int c = 0; c < 2; c++) {
            uint4 raw = __ldcs(gp + c * 32 + lane);
            const __half2* h2 = (const __half2*)&raw;
            #pragma unroll
            for (int q = 0; q < 4; q++) {
                float2 v = __half22float2(h2[q]);
                og[c*8 + q*2 + 0] = fmaf(fnw, v.x, og[c*8 + q*2 + 0]);
                og[c*8 + q*2 + 1] = fmaf(fnw, v.y, og[c*8 + q*2 + 1]);
            }
        }
    }

    #pragma unroll
    for (int c = 0; c < 2; c++) {
        int d = (c * 32 + lane) * 8;
        *(float4*)&out[(size_t)n * DIM + d] =
            make_float4(op[c*8+0], op[c*8+1], op[c*8+2], op[c*8+3]);
        *(float4*)&out[(size_t)n * DIM + d + 4] =
            make_float4(op[c*8+4], op[c*8+5], op[c*8+6], op[c*8+7]);
        *(float4*)&out[((size_t)N_TOK + n) * DIM + d] =
            make_float4(og[c*8+0], og[c*8+1], og[c*8+2], og[c*8+3]);
        *(float4*)&out[((size_t)N_TOK + n) * DIM + d + 4] =
            make_float4(og[c*8+4], og[c*8+5], og[c*8+6], og[c*8+7]);
    }
}

// ---------------------------------------------------------------------------
extern "C" void kernel_launch(void* const* d_in, const int* in_sizes, int n_in,
                              void* d_out, int out_size) {
    const float* token  = (const float*)d_in[0];
    const float* routed = (const float*)d_in[1];
    const float* sim    = (const float*)d_in[2];
    const float* selW   = (const float*)d_in[3];
    const float* selb   = (const float*)d_in[4];
    const float* netW   = (const float*)d_in[5];
    const float* netb   = (const float*)d_in[6];
    const float* lng    = (const float*)d_in[7];
    const float* lnb    = (const float*)d_in[8];
    const float* gateW  = (const float*)d_in[9];
    const float* gateb  = (const float*)d_in[10];
    float* out = (float*)d_out;

    const int smem_bytes = 3 * SM_STAGE + 1024;   // 99328 -> 2 CTAs/SM
    cudaFuncSetAttribute(gemm_kernel,
                         cudaFuncAttributeMaxDynamicSharedMemorySize, smem_bytes);

    prep_kernel<<<N_TOK + CONV_BLOCKS, 128>>>(token, routed, sim, selW, selb,
                                              netW, gateW);
    gemm_kernel<<<dim3(128, 4, 16), 256, smem_bytes>>>(netb, gateb);
    combine_kernel<<<N_TOK / 8, 256>>>(lng, lnb, out);
}